// round 10
// baseline (speedup 1.0000x reference)
#include <cuda_runtime.h>
#include <cuda_fp16.h>
#include <cstdint>

// ---------------- problem constants ----------------
#define NN   50000
#define EE   800000
#define FIN  128
#define HH   4
#define CC1  64
#define CC2  32
#define NEG_SLOPE 0.2f
#define EPSV 1e-16f

#define SCAN_CHUNK 256
#define NB ((NN + SCAN_CHUNK - 1) / SCAN_CHUNK)   // 196

// ---------------- device scratch (no allocs allowed) ----------------
__device__ __half g_feat[NN * HH * CC1];  // h stored fp16 (only consumer: gather)
__device__ float g_hmid[NN * CC1];        // layer1 output (fp32) [N,64]
__device__ float g_as[NN * HH];
__device__ float g_ad[NN * HH];
__device__ int   g_src[EE];
__device__ int   g_dst[EE];
__device__ int   g_deg[NN];
__device__ int   g_rowptr[NN + 1];
__device__ int   g_cursor[NN];
__device__ int   g_csr_src[EE];
__device__ int   g_partial[NB];
__device__ int   g_offset[NB];

// ---------------- CSR build kernels ----------------

__global__ void zero_deg_kernel(int* __restrict__ deg) {
    int i = blockIdx.x * blockDim.x + threadIdx.x;
    int stride = gridDim.x * blockDim.x;
    for (; i < NN; i += stride) deg[i] = 0;
}

// Decode edge_index into int src/dst + in-degree histogram.
// Detects int32 vs int64 on device (false-positive prob ~(1/NN)^8 ~= 0).
__global__ void decode_hist_kernel(const void* __restrict__ ei_raw,
                                   int* __restrict__ src, int* __restrict__ dst,
                                   int* __restrict__ deg) {
    const long long* p64 = (const long long*)ei_raw;
    bool is64 = true;
#pragma unroll
    for (int k = 0; k < 8; k++) {
        long long v = p64[k];
        if (v < 0 || v >= NN) { is64 = false; break; }
    }
    int i = blockIdx.x * blockDim.x + threadIdx.x;
    int stride = gridDim.x * blockDim.x;
    if (is64) {
        for (; i < EE; i += stride) {
            int s = (int)p64[i];
            int d = (int)p64[EE + i];
            src[i] = s; dst[i] = d;
            atomicAdd(&deg[d], 1);
        }
    } else {
        const int* p32 = (const int*)ei_raw;
        for (; i < EE; i += stride) {
            int s = p32[i];
            int d = p32[EE + i];
            src[i] = s; dst[i] = d;
            atomicAdd(&deg[d], 1);
        }
    }
}

// Phase A: per-chunk sums.
__global__ void scan_partials_kernel(const int* __restrict__ deg, int* __restrict__ partial) {
    __shared__ int sm[SCAN_CHUNK];
    int b = blockIdx.x, t = threadIdx.x;
    int i = b * SCAN_CHUNK + t;
    sm[t] = (i < NN) ? deg[i] : 0;
    __syncthreads();
#pragma unroll
    for (int off = 128; off; off >>= 1) {
        if (t < off) sm[t] += sm[t + off];
        __syncthreads();
    }
    if (t == 0) partial[b] = sm[0];
}

// Phase B: single-block exclusive scan of NB partials.
__global__ void scan_offsets_kernel(const int* __restrict__ partial,
                                    int* __restrict__ offset, int* __restrict__ rowptr) {
    __shared__ int sm[256];
    int t = threadIdx.x;
    int v = (t < NB) ? partial[t] : 0;
    sm[t] = v;
    __syncthreads();
#pragma unroll
    for (int off = 1; off < 256; off <<= 1) {
        int x = (t >= off) ? sm[t - off] : 0;
        __syncthreads();
        sm[t] += x;
        __syncthreads();
    }
    if (t < NB) offset[t] = sm[t] - v;  // exclusive
    if (t == 0) rowptr[NN] = EE;
}

// Phase C: per-chunk local exclusive scan + block offset -> rowptr/cursor.
__global__ void scan_final_kernel(const int* __restrict__ deg, const int* __restrict__ offset,
                                  int* __restrict__ rowptr, int* __restrict__ cursor) {
    __shared__ int sm[SCAN_CHUNK];
    int b = blockIdx.x, t = threadIdx.x;
    int i = b * SCAN_CHUNK + t;
    int v = (i < NN) ? deg[i] : 0;
    sm[t] = v;
    __syncthreads();
#pragma unroll
    for (int off = 1; off < SCAN_CHUNK; off <<= 1) {
        int x = (t >= off) ? sm[t - off] : 0;
        __syncthreads();
        sm[t] += x;
        __syncthreads();
    }
    if (i < NN) {
        int excl = sm[t] - v + offset[b];
        rowptr[i] = excl;
        cursor[i] = excl;
    }
}

// Scatter edge source ids into CSR slots grouped by dst.
__global__ void fill_csr_kernel(const int* __restrict__ src, const int* __restrict__ dst,
                                int* __restrict__ cursor, int* __restrict__ csr_src) {
    int i = blockIdx.x * blockDim.x + threadIdx.x;
    int stride = gridDim.x * blockDim.x;
    for (; i < EE; i += stride) {
        int d = dst[i];
        int slot = atomicAdd(&cursor[d], 1);
        csr_src[slot] = src[i];
    }
}

// ---------------- fused GEMM + attention-dot epilogue, fp16 output ----------------
// C[n,M] = A[n,K] @ B[K,M]; BM=128, BN=64, BK=16, 256 threads, 8x4 microtile.
// Epilogue: (a) converts acc to half2 and writes feat; (b) dots acc against
// att vectors with shfl reduction (head-aligned col tiles) writing a_s/a_d.
template <int C>
__global__ void __launch_bounds__(256) gemm_fused_kernel(
        const float* __restrict__ A, const float* __restrict__ B,
        __half* __restrict__ Cout, int n, int K,
        const float* __restrict__ att_s, const float* __restrict__ att_d,
        float* __restrict__ as_o, float* __restrict__ ad_o) {
    const int M = HH * C;
    __shared__ float As[16][128];
    __shared__ float Bs[16][64];
    int tid = threadIdx.x;
    int tx = tid & 15;        // col group (4 cols)
    int ty = tid >> 4;        // row group (8 rows)
    int rowBase = blockIdx.y * 128;
    int colBase = blockIdx.x * 64;

    // attention vector slice for this thread's 4 columns
    int head, cloc;
    if (C == 64) { head = blockIdx.x;                 cloc = tx * 4; }
    else         { head = blockIdx.x * 2 + (tx >> 3); cloc = (tx & 7) * 4; }
    float satt[4], datt[4];
#pragma unroll
    for (int j = 0; j < 4; j++) {
        satt[j] = __ldg(&att_s[head * C + cloc + j]);
        datt[j] = __ldg(&att_d[head * C + cloc + j]);
    }

    float acc[8][4];
#pragma unroll
    for (int i = 0; i < 8; i++)
#pragma unroll
        for (int j = 0; j < 4; j++) acc[i][j] = 0.f;

    for (int k0 = 0; k0 < K; k0 += 16) {
#pragma unroll
        for (int q = 0; q < 2; q++) {
            int idx = tid + q * 256;
            int r = idx >> 2;
            int kq = idx & 3;
            int row = rowBase + r;
            float4 v = (row < n) ? ((const float4*)(A + (size_t)row * K + k0))[kq]
                                 : make_float4(0.f, 0.f, 0.f, 0.f);
            As[kq * 4 + 0][r] = v.x;
            As[kq * 4 + 1][r] = v.y;
            As[kq * 4 + 2][r] = v.z;
            As[kq * 4 + 3][r] = v.w;
        }
        {
            int r = tid >> 4;
            int cq = tid & 15;
            float4 v = ((const float4*)(B + (size_t)(k0 + r) * M + colBase))[cq];
            ((float4*)&Bs[r][0])[cq] = v;
        }
        __syncthreads();
#pragma unroll
        for (int kk = 0; kk < 16; kk++) {
            float a[8], b[4];
            float4 a0 = ((const float4*)&As[kk][0])[ty * 2];
            float4 a1 = ((const float4*)&As[kk][0])[ty * 2 + 1];
            a[0] = a0.x; a[1] = a0.y; a[2] = a0.z; a[3] = a0.w;
            a[4] = a1.x; a[5] = a1.y; a[6] = a1.z; a[7] = a1.w;
            float4 bv = ((const float4*)&Bs[kk][0])[tx];
            b[0] = bv.x; b[1] = bv.y; b[2] = bv.z; b[3] = bv.w;
#pragma unroll
            for (int i = 0; i < 8; i++)
#pragma unroll
                for (int j = 0; j < 4; j++) acc[i][j] += a[i] * b[j];
        }
        __syncthreads();
    }

    const int W = (C == 64) ? 16 : 8;   // shfl reduction width (lanes per head seg)
#pragma unroll
    for (int i = 0; i < 8; i++) {
        int r = rowBase + ty * 8 + i;
        if (r < n) {
            __half2 h0 = __float22half2_rn(make_float2(acc[i][0], acc[i][1]));
            __half2 h1 = __float22half2_rn(make_float2(acc[i][2], acc[i][3]));
            __half2* dstp = (__half2*)(Cout + (size_t)r * M + colBase);
            dstp[tx * 2]     = h0;
            dstp[tx * 2 + 1] = h1;
        }
        float ps = acc[i][0] * satt[0] + acc[i][1] * satt[1] +
                   acc[i][2] * satt[2] + acc[i][3] * satt[3];
        float pd = acc[i][0] * datt[0] + acc[i][1] * datt[1] +
                   acc[i][2] * datt[2] + acc[i][3] * datt[3];
#pragma unroll
        for (int o = W / 2; o; o >>= 1) {
            ps += __shfl_down_sync(0xffffffffu, ps, o, W);
            pd += __shfl_down_sync(0xffffffffu, pd, o, W);
        }
        if ((tx & (W - 1)) == 0 && r < n) {
            as_o[r * HH + head] = ps;
            ad_o[r * HH + head] = pd;
        }
    }
}

// ---------------- fused pull-mode GAT aggregation (fp16 gather) ----------------
// One block per destination node; NT = HH*C/2 threads; thread t owns channels
// [2t, 2t+1] (one half2). All accumulation in fp32.
template <int C>
__global__ void __launch_bounds__(HH * C / 2) gat_aggregate_kernel(
        const int* __restrict__ rowptr,
        const int* __restrict__ csr_src,
        const float* __restrict__ as_i,
        const float* __restrict__ ad_i,
        const __half2* __restrict__ feat,   // [N, HH*C/2]
        const float* __restrict__ bias,
        float* __restrict__ out, int do_relu) {
    constexpr int NT = HH * C / 2;       // 128 (C=64) or 64 (C=32)
    __shared__ float sm[HH * C];
    const int node = blockIdx.x;
    const int t = threadIdx.x;
    const int head = (2 * t) / C;
    const float adh = ad_i[node * HH + head];
    int beg = rowptr[node], end = rowptr[node + 1];
    float acc0 = 0.f, acc1 = 0.f, denom = 0.f;

    int e = beg;
    for (; e + 4 <= end; e += 4) {
        int s0 = __ldg(&csr_src[e]);
        int s1 = __ldg(&csr_src[e + 1]);
        int s2 = __ldg(&csr_src[e + 2]);
        int s3 = __ldg(&csr_src[e + 3]);
        float a0 = __ldg(&as_i[s0 * HH + head]);
        float a1 = __ldg(&as_i[s1 * HH + head]);
        float a2 = __ldg(&as_i[s2 * HH + head]);
        float a3 = __ldg(&as_i[s3 * HH + head]);
        float2 u0 = __half22float2(feat[(size_t)s0 * NT + t]);
        float2 u1 = __half22float2(feat[(size_t)s1 * NT + t]);
        float2 u2 = __half22float2(feat[(size_t)s2 * NT + t]);
        float2 u3 = __half22float2(feat[(size_t)s3 * NT + t]);
        float e0 = a0 + adh; e0 = e0 > 0.f ? e0 : NEG_SLOPE * e0;
        float e1 = a1 + adh; e1 = e1 > 0.f ? e1 : NEG_SLOPE * e1;
        float e2 = a2 + adh; e2 = e2 > 0.f ? e2 : NEG_SLOPE * e2;
        float e3 = a3 + adh; e3 = e3 > 0.f ? e3 : NEG_SLOPE * e3;
        float x0 = __expf(e0), x1 = __expf(e1), x2 = __expf(e2), x3 = __expf(e3);
        denom += (x0 + x1) + (x2 + x3);
        acc0 += (x0 * u0.x + x1 * u1.x) + (x2 * u2.x + x3 * u3.x);
        acc1 += (x0 * u0.y + x1 * u1.y) + (x2 * u2.y + x3 * u3.y);
    }
    for (; e < end; e++) {
        int s0 = __ldg(&csr_src[e]);
        float a0 = __ldg(&as_i[s0 * HH + head]);
        float2 u0 = __half22float2(feat[(size_t)s0 * NT + t]);
        float e0 = a0 + adh; e0 = e0 > 0.f ? e0 : NEG_SLOPE * e0;
        float x0 = __expf(e0);
        denom += x0;
        acc0 += x0 * u0.x;
        acc1 += x0 * u0.y;
    }

    float inv = 1.f / (denom + EPSV);
    sm[2 * t]     = acc0 * inv;
    sm[2 * t + 1] = acc1 * inv;
    __syncthreads();
    if (t < C) {
        float v = 0.25f * (sm[t] + sm[C + t] + sm[2 * C + t] + sm[3 * C + t]) + bias[t];
        if (do_relu) v = fmaxf(v, 0.f);
        out[(size_t)node * C + t] = v;
    }
}

// ---------------- host launcher ----------------
extern "C" void kernel_launch(void* const* d_in, const int* in_sizes, int n_in,
                              void* d_out, int out_size) {
    const float* x   = (const float*)d_in[0];
    const void*  ei  = d_in[1];
    const float* W1  = (const float*)d_in[2];
    const float* as1 = (const float*)d_in[3];
    const float* ad1 = (const float*)d_in[4];
    const float* b1  = (const float*)d_in[5];
    const float* W2  = (const float*)d_in[6];
    const float* as2 = (const float*)d_in[7];
    const float* ad2 = (const float*)d_in[8];
    const float* b2  = (const float*)d_in[9];
    float* out = (float*)d_out;

    __half* feat;
    float *hmid, *asb, *adb;
    int *srcp, *dstp, *deg, *rowptr, *cursor, *csr, *partial, *offset;
    cudaGetSymbolAddress((void**)&feat,    g_feat);
    cudaGetSymbolAddress((void**)&hmid,    g_hmid);
    cudaGetSymbolAddress((void**)&asb,     g_as);
    cudaGetSymbolAddress((void**)&adb,     g_ad);
    cudaGetSymbolAddress((void**)&srcp,    g_src);
    cudaGetSymbolAddress((void**)&dstp,    g_dst);
    cudaGetSymbolAddress((void**)&deg,     g_deg);
    cudaGetSymbolAddress((void**)&rowptr,  g_rowptr);
    cudaGetSymbolAddress((void**)&cursor,  g_cursor);
    cudaGetSymbolAddress((void**)&csr,     g_csr_src);
    cudaGetSymbolAddress((void**)&partial, g_partial);
    cudaGetSymbolAddress((void**)&offset,  g_offset);

    // ---- CSR build ----
    zero_deg_kernel<<<256, 256>>>(deg);
    decode_hist_kernel<<<1024, 256>>>(ei, srcp, dstp, deg);
    scan_partials_kernel<<<NB, SCAN_CHUNK>>>(deg, partial);
    scan_offsets_kernel<<<1, 256>>>(partial, offset, rowptr);
    scan_final_kernel<<<NB, SCAN_CHUNK>>>(deg, offset, rowptr, cursor);
    fill_csr_kernel<<<1024, 256>>>(srcp, dstp, cursor, csr);

    // ---- layer 1 ----
    {
        dim3 ggrid(HH * CC1 / 64, (NN + 127) / 128);
        gemm_fused_kernel<CC1><<<ggrid, 256>>>(x, W1, feat, NN, FIN, as1, ad1, asb, adb);
        gat_aggregate_kernel<CC1><<<NN, HH * CC1 / 2>>>(
            rowptr, csr, asb, adb, (const __half2*)feat, b1, hmid, 1);
    }

    // ---- layer 2 ----
    {
        dim3 ggrid(HH * CC2 / 64, (NN + 127) / 128);
        gemm_fused_kernel<CC2><<<ggrid, 256>>>(hmid, W2, feat, NN, CC1, as2, ad2, asb, adb);
        gat_aggregate_kernel<CC2><<<NN, HH * CC2 / 2>>>(
            rowptr, csr, asb, adb, (const __half2*)feat, b2, out, 0);
    }
}

// round 11
// speedup vs baseline: 1.5923x; 1.5923x over previous
#include <cuda_runtime.h>
#include <cuda_fp16.h>
#include <cstdint>

// ---------------- problem constants ----------------
#define NN   50000
#define EE   800000
#define FIN  128
#define HH   4
#define CC1  64
#define CC2  32
#define NEG_SLOPE 0.2f
#define EPSV 1e-16f

#define SCAN_CHUNK 256
#define NB ((NN + SCAN_CHUNK - 1) / SCAN_CHUNK)   // 196

// ---------------- device scratch (no allocs allowed) ----------------
__device__ __half g_feat[NN * HH * CC1];  // h stored fp16 (only consumer: gather)
__device__ float g_hmid[NN * CC1];        // layer1 output (fp32) [N,64]
__device__ float g_as[NN * HH];
__device__ float g_ad[NN * HH];
__device__ int   g_src[EE];
__device__ int   g_dst[EE];
__device__ int   g_deg[NN];
__device__ int   g_rowptr[NN + 1];
__device__ int   g_cursor[NN];
__device__ int   g_csr_src[EE];
__device__ int   g_partial[NB];
__device__ int   g_offset[NB];

// ---------------- CSR build kernels ----------------

// Decode edge_index into int src/dst + in-degree histogram.
// Detects int32 vs int64 on device (false-positive prob ~(1/NN)^8 ~= 0).
__global__ void decode_hist_kernel(const void* __restrict__ ei_raw,
                                   int* __restrict__ src, int* __restrict__ dst,
                                   int* __restrict__ deg) {
    const long long* p64 = (const long long*)ei_raw;
    bool is64 = true;
#pragma unroll
    for (int k = 0; k < 8; k++) {
        long long v = p64[k];
        if (v < 0 || v >= NN) { is64 = false; break; }
    }
    int i = blockIdx.x * blockDim.x + threadIdx.x;
    int stride = gridDim.x * blockDim.x;
    if (is64) {
        for (; i < EE; i += stride) {
            int s = (int)p64[i];
            int d = (int)p64[EE + i];
            src[i] = s; dst[i] = d;
            atomicAdd(&deg[d], 1);
        }
    } else {
        const int* p32 = (const int*)ei_raw;
        for (; i < EE; i += stride) {
            int s = p32[i];
            int d = p32[EE + i];
            src[i] = s; dst[i] = d;
            atomicAdd(&deg[d], 1);
        }
    }
}

// Phase A: per-chunk sums.
__global__ void scan_partials_kernel(const int* __restrict__ deg, int* __restrict__ partial) {
    __shared__ int sm[SCAN_CHUNK];
    int b = blockIdx.x, t = threadIdx.x;
    int i = b * SCAN_CHUNK + t;
    sm[t] = (i < NN) ? deg[i] : 0;
    __syncthreads();
#pragma unroll
    for (int off = 128; off; off >>= 1) {
        if (t < off) sm[t] += sm[t + off];
        __syncthreads();
    }
    if (t == 0) partial[b] = sm[0];
}

// Phase B: single-block exclusive scan of NB partials.
__global__ void scan_offsets_kernel(const int* __restrict__ partial,
                                    int* __restrict__ offset, int* __restrict__ rowptr) {
    __shared__ int sm[256];
    int t = threadIdx.x;
    int v = (t < NB) ? partial[t] : 0;
    sm[t] = v;
    __syncthreads();
#pragma unroll
    for (int off = 1; off < 256; off <<= 1) {
        int x = (t >= off) ? sm[t - off] : 0;
        __syncthreads();
        sm[t] += x;
        __syncthreads();
    }
    if (t < NB) offset[t] = sm[t] - v;  // exclusive
    if (t == 0) rowptr[NN] = EE;
}

// Phase C: per-chunk local exclusive scan + block offset -> rowptr/cursor.
__global__ void scan_final_kernel(const int* __restrict__ deg, const int* __restrict__ offset,
                                  int* __restrict__ rowptr, int* __restrict__ cursor) {
    __shared__ int sm[SCAN_CHUNK];
    int b = blockIdx.x, t = threadIdx.x;
    int i = b * SCAN_CHUNK + t;
    int v = (i < NN) ? deg[i] : 0;
    sm[t] = v;
    __syncthreads();
#pragma unroll
    for (int off = 1; off < SCAN_CHUNK; off <<= 1) {
        int x = (t >= off) ? sm[t - off] : 0;
        __syncthreads();
        sm[t] += x;
        __syncthreads();
    }
    if (i < NN) {
        int excl = sm[t] - v + offset[b];
        rowptr[i] = excl;
        cursor[i] = excl;
    }
}

// Scatter edge source ids into CSR slots grouped by dst.
__global__ void fill_csr_kernel(const int* __restrict__ src, const int* __restrict__ dst,
                                int* __restrict__ cursor, int* __restrict__ csr_src) {
    int i = blockIdx.x * blockDim.x + threadIdx.x;
    int stride = gridDim.x * blockDim.x;
    for (; i < EE; i += stride) {
        int d = dst[i];
        int slot = atomicAdd(&cursor[d], 1);
        csr_src[slot] = src[i];
    }
}

// ---------------- fused GEMM + attention-dot epilogue, fp16 output ----------------
// C[n,M] = A[n,K] @ B[K,M]; BM=128, BN=64, BK=16, 256 threads, 8x4 microtile.
template <int C>
__global__ void __launch_bounds__(256) gemm_fused_kernel(
        const float* __restrict__ A, const float* __restrict__ B,
        __half* __restrict__ Cout, int n, int K,
        const float* __restrict__ att_s, const float* __restrict__ att_d,
        float* __restrict__ as_o, float* __restrict__ ad_o) {
    const int M = HH * C;
    __shared__ float As[16][128];
    __shared__ float Bs[16][64];
    int tid = threadIdx.x;
    int tx = tid & 15;        // col group (4 cols)
    int ty = tid >> 4;        // row group (8 rows)
    int rowBase = blockIdx.y * 128;
    int colBase = blockIdx.x * 64;

    // attention vector slice for this thread's 4 columns
    int head, cloc;
    if (C == 64) { head = blockIdx.x;                 cloc = tx * 4; }
    else         { head = blockIdx.x * 2 + (tx >> 3); cloc = (tx & 7) * 4; }
    float satt[4], datt[4];
#pragma unroll
    for (int j = 0; j < 4; j++) {
        satt[j] = __ldg(&att_s[head * C + cloc + j]);
        datt[j] = __ldg(&att_d[head * C + cloc + j]);
    }

    float acc[8][4];
#pragma unroll
    for (int i = 0; i < 8; i++)
#pragma unroll
        for (int j = 0; j < 4; j++) acc[i][j] = 0.f;

    for (int k0 = 0; k0 < K; k0 += 16) {
#pragma unroll
        for (int q = 0; q < 2; q++) {
            int idx = tid + q * 256;
            int r = idx >> 2;
            int kq = idx & 3;
            int row = rowBase + r;
            float4 v = (row < n) ? ((const float4*)(A + (size_t)row * K + k0))[kq]
                                 : make_float4(0.f, 0.f, 0.f, 0.f);
            As[kq * 4 + 0][r] = v.x;
            As[kq * 4 + 1][r] = v.y;
            As[kq * 4 + 2][r] = v.z;
            As[kq * 4 + 3][r] = v.w;
        }
        {
            int r = tid >> 4;
            int cq = tid & 15;
            float4 v = ((const float4*)(B + (size_t)(k0 + r) * M + colBase))[cq];
            ((float4*)&Bs[r][0])[cq] = v;
        }
        __syncthreads();
#pragma unroll
        for (int kk = 0; kk < 16; kk++) {
            float a[8], b[4];
            float4 a0 = ((const float4*)&As[kk][0])[ty * 2];
            float4 a1 = ((const float4*)&As[kk][0])[ty * 2 + 1];
            a[0] = a0.x; a[1] = a0.y; a[2] = a0.z; a[3] = a0.w;
            a[4] = a1.x; a[5] = a1.y; a[6] = a1.z; a[7] = a1.w;
            float4 bv = ((const float4*)&Bs[kk][0])[tx];
            b[0] = bv.x; b[1] = bv.y; b[2] = bv.z; b[3] = bv.w;
#pragma unroll
            for (int i = 0; i < 8; i++)
#pragma unroll
                for (int j = 0; j < 4; j++) acc[i][j] += a[i] * b[j];
        }
        __syncthreads();
    }

    const int W = (C == 64) ? 16 : 8;   // shfl reduction width (lanes per head seg)
#pragma unroll
    for (int i = 0; i < 8; i++) {
        int r = rowBase + ty * 8 + i;
        if (r < n) {
            __half2 h0 = __float22half2_rn(make_float2(acc[i][0], acc[i][1]));
            __half2 h1 = __float22half2_rn(make_float2(acc[i][2], acc[i][3]));
            // one 8-byte store (half2x2) instead of two 4-byte stores
            float2 packed = make_float2(__half2float(h0.x) * 0.f, 0.f); // placeholder avoided below
            __half2 hh[2] = {h0, h1};
            *(uint2*)((__half2*)(Cout + (size_t)r * M + colBase) + tx * 2) =
                *(const uint2*)hh;
        }
        float ps = acc[i][0] * satt[0] + acc[i][1] * satt[1] +
                   acc[i][2] * satt[2] + acc[i][3] * satt[3];
        float pd = acc[i][0] * datt[0] + acc[i][1] * datt[1] +
                   acc[i][2] * datt[2] + acc[i][3] * datt[3];
#pragma unroll
        for (int o = W / 2; o; o >>= 1) {
            ps += __shfl_down_sync(0xffffffffu, ps, o, W);
            pd += __shfl_down_sync(0xffffffffu, pd, o, W);
        }
        if ((tx & (W - 1)) == 0 && r < n) {
            as_o[r * HH + head] = ps;
            ad_o[r * HH + head] = pd;
        }
    }
}

// ---------------- fused pull-mode GAT aggregation (fp16 gather, unroll 8) ----------------
// One block per destination node; NT = HH*C/2 threads; thread t owns channels
// [2t, 2t+1] (one half2). All accumulation in fp32.
template <int C>
__global__ void __launch_bounds__(HH * C / 2) gat_aggregate_kernel(
        const int* __restrict__ rowptr,
        const int* __restrict__ csr_src,
        const float* __restrict__ as_i,
        const float* __restrict__ ad_i,
        const __half2* __restrict__ feat,   // [N, HH*C/2]
        const float* __restrict__ bias,
        float* __restrict__ out, int do_relu) {
    constexpr int NT = HH * C / 2;       // 128 (C=64) or 64 (C=32)
    __shared__ float sm[HH * C];
    const int node = blockIdx.x;
    const int t = threadIdx.x;
    const int head = (2 * t) / C;
    const float adh = ad_i[node * HH + head];
    int beg = rowptr[node], end = rowptr[node + 1];
    float acc0 = 0.f, acc1 = 0.f, denom = 0.f;

    int e = beg;
    // unroll-8 main loop: 8 independent gathers in flight per warp
    for (; e + 8 <= end; e += 8) {
        int s[8];
        float a[8];
        __half2 u[8];
#pragma unroll
        for (int q = 0; q < 8; q++) s[q] = __ldg(&csr_src[e + q]);
#pragma unroll
        for (int q = 0; q < 8; q++) u[q] = feat[(size_t)s[q] * NT + t];
#pragma unroll
        for (int q = 0; q < 8; q++) a[q] = __ldg(&as_i[s[q] * HH + head]);
#pragma unroll
        for (int q = 0; q < 8; q++) {
            float eq = a[q] + adh; eq = eq > 0.f ? eq : NEG_SLOPE * eq;
            float xq = __expf(eq);
            float2 uf = __half22float2(u[q]);
            denom += xq;
            acc0 += xq * uf.x;
            acc1 += xq * uf.y;
        }
    }
    for (; e + 4 <= end; e += 4) {
        int s[4];
        float a[4];
        __half2 u[4];
#pragma unroll
        for (int q = 0; q < 4; q++) s[q] = __ldg(&csr_src[e + q]);
#pragma unroll
        for (int q = 0; q < 4; q++) u[q] = feat[(size_t)s[q] * NT + t];
#pragma unroll
        for (int q = 0; q < 4; q++) a[q] = __ldg(&as_i[s[q] * HH + head]);
#pragma unroll
        for (int q = 0; q < 4; q++) {
            float eq = a[q] + adh; eq = eq > 0.f ? eq : NEG_SLOPE * eq;
            float xq = __expf(eq);
            float2 uf = __half22float2(u[q]);
            denom += xq;
            acc0 += xq * uf.x;
            acc1 += xq * uf.y;
        }
    }
    for (; e < end; e++) {
        int s0 = __ldg(&csr_src[e]);
        float a0 = __ldg(&as_i[s0 * HH + head]);
        float2 u0 = __half22float2(feat[(size_t)s0 * NT + t]);
        float e0 = a0 + adh; e0 = e0 > 0.f ? e0 : NEG_SLOPE * e0;
        float x0 = __expf(e0);
        denom += x0;
        acc0 += x0 * u0.x;
        acc1 += x0 * u0.y;
    }

    float inv = 1.f / (denom + EPSV);
    sm[2 * t]     = acc0 * inv;
    sm[2 * t + 1] = acc1 * inv;
    __syncthreads();
    if (t < C) {
        float v = 0.25f * (sm[t] + sm[C + t] + sm[2 * C + t] + sm[3 * C + t]) + bias[t];
        if (do_relu) v = fmaxf(v, 0.f);
        out[(size_t)node * C + t] = v;
    }
}

// ---------------- host launcher ----------------
extern "C" void kernel_launch(void* const* d_in, const int* in_sizes, int n_in,
                              void* d_out, int out_size) {
    const float* x   = (const float*)d_in[0];
    const void*  ei  = d_in[1];
    const float* W1  = (const float*)d_in[2];
    const float* as1 = (const float*)d_in[3];
    const float* ad1 = (const float*)d_in[4];
    const float* b1  = (const float*)d_in[5];
    const float* W2  = (const float*)d_in[6];
    const float* as2 = (const float*)d_in[7];
    const float* ad2 = (const float*)d_in[8];
    const float* b2  = (const float*)d_in[9];
    float* out = (float*)d_out;

    __half* feat;
    float *hmid, *asb, *adb;
    int *srcp, *dstp, *deg, *rowptr, *cursor, *csr, *partial, *offset;
    cudaGetSymbolAddress((void**)&feat,    g_feat);
    cudaGetSymbolAddress((void**)&hmid,    g_hmid);
    cudaGetSymbolAddress((void**)&asb,     g_as);
    cudaGetSymbolAddress((void**)&adb,     g_ad);
    cudaGetSymbolAddress((void**)&srcp,    g_src);
    cudaGetSymbolAddress((void**)&dstp,    g_dst);
    cudaGetSymbolAddress((void**)&deg,     g_deg);
    cudaGetSymbolAddress((void**)&rowptr,  g_rowptr);
    cudaGetSymbolAddress((void**)&cursor,  g_cursor);
    cudaGetSymbolAddress((void**)&csr,     g_csr_src);
    cudaGetSymbolAddress((void**)&partial, g_partial);
    cudaGetSymbolAddress((void**)&offset,  g_offset);

    // ---- CSR build ----
    cudaMemsetAsync(deg, 0, NN * sizeof(int));
    decode_hist_kernel<<<1024, 256>>>(ei, srcp, dstp, deg);
    scan_partials_kernel<<<NB, SCAN_CHUNK>>>(deg, partial);
    scan_offsets_kernel<<<1, 256>>>(partial, offset, rowptr);
    scan_final_kernel<<<NB, SCAN_CHUNK>>>(deg, offset, rowptr, cursor);
    fill_csr_kernel<<<512, 256>>>(srcp, dstp, cursor, csr);

    // ---- layer 1 ----
    {
        dim3 ggrid(HH * CC1 / 64, (NN + 127) / 128);
        gemm_fused_kernel<CC1><<<ggrid, 256>>>(x, W1, feat, NN, FIN, as1, ad1, asb, adb);
        gat_aggregate_kernel<CC1><<<NN, HH * CC1 / 2>>>(
            rowptr, csr, asb, adb, (const __half2*)feat, b1, hmid, 1);
    }

    // ---- layer 2 ----
    {
        dim3 ggrid(HH * CC2 / 64, (NN + 127) / 128);
        gemm_fused_kernel<CC2><<<ggrid, 256>>>(hmid, W2, feat, NN, CC1, as2, ad2, asb, adb);
        gat_aggregate_kernel<CC2><<<NN, HH * CC2 / 2>>>(
            rowptr, csr, asb, adb, (const __half2*)feat, b2, out, 0);
    }
}

// round 12
// speedup vs baseline: 1.8832x; 1.1827x over previous
#include <cuda_runtime.h>
#include <cuda_fp16.h>
#include <cstdint>

// ---------------- problem constants ----------------
#define NN   50000
#define EE   800000
#define FIN  128
#define HH   4
#define CC1  64
#define CC2  32
#define NEG_SLOPE 0.2f
#define EPSV 1e-16f

#define SCAN_CHUNK 256
#define NB ((NN + SCAN_CHUNK - 1) / SCAN_CHUNK)   // 196

// ---------------- device scratch (no allocs allowed) ----------------
__device__ __half g_feat[NN * HH * CC1];   // h per layer, fp16
__device__ __half g_hmid[NN * CC1];        // layer1 output, fp16 (input to layer2 MMA)
__device__ __half g_xh[NN * FIN];          // x converted to fp16
__device__ __half g_w1h[FIN * HH * CC1];
__device__ __half g_w2h[CC1 * HH * CC2];
__device__ float g_as[NN * HH];
__device__ float g_ad[NN * HH];
__device__ int   g_src[EE];
__device__ int   g_dst[EE];
__device__ int   g_deg[NN];
__device__ int   g_rowptr[NN + 1];
__device__ int   g_cursor[NN];
__device__ int   g_csr_src[EE];
__device__ int   g_partial[NB];
__device__ int   g_offset[NB];

// ---------------- fp32 -> fp16 convert ----------------
__global__ void f2h_kernel(const float* __restrict__ in, __half* __restrict__ out, int n4) {
    int i = blockIdx.x * blockDim.x + threadIdx.x;
    int stride = gridDim.x * blockDim.x;
    for (; i < n4; i += stride) {
        float4 v = ((const float4*)in)[i];
        __half2 h0 = __float22half2_rn(make_float2(v.x, v.y));
        __half2 h1 = __float22half2_rn(make_float2(v.z, v.w));
        ((__half2*)out)[i * 2]     = h0;
        ((__half2*)out)[i * 2 + 1] = h1;
    }
}

// ---------------- CSR build kernels ----------------

// Decode edge_index into int src/dst + in-degree histogram.
// Detects int32 vs int64 on device (false-positive prob ~(1/NN)^8 ~= 0).
__global__ void decode_hist_kernel(const void* __restrict__ ei_raw,
                                   int* __restrict__ src, int* __restrict__ dst,
                                   int* __restrict__ deg) {
    const long long* p64 = (const long long*)ei_raw;
    bool is64 = true;
#pragma unroll
    for (int k = 0; k < 8; k++) {
        long long v = p64[k];
        if (v < 0 || v >= NN) { is64 = false; break; }
    }
    int i = blockIdx.x * blockDim.x + threadIdx.x;
    int stride = gridDim.x * blockDim.x;
    if (is64) {
        for (; i < EE; i += stride) {
            int s = (int)p64[i];
            int d = (int)p64[EE + i];
            src[i] = s; dst[i] = d;
            atomicAdd(&deg[d], 1);
        }
    } else {
        const int* p32 = (const int*)ei_raw;
        for (; i < EE; i += stride) {
            int s = p32[i];
            int d = p32[EE + i];
            src[i] = s; dst[i] = d;
            atomicAdd(&deg[d], 1);
        }
    }
}

__global__ void scan_partials_kernel(const int* __restrict__ deg, int* __restrict__ partial) {
    __shared__ int sm[SCAN_CHUNK];
    int b = blockIdx.x, t = threadIdx.x;
    int i = b * SCAN_CHUNK + t;
    sm[t] = (i < NN) ? deg[i] : 0;
    __syncthreads();
#pragma unroll
    for (int off = 128; off; off >>= 1) {
        if (t < off) sm[t] += sm[t + off];
        __syncthreads();
    }
    if (t == 0) partial[b] = sm[0];
}

__global__ void scan_offsets_kernel(const int* __restrict__ partial,
                                    int* __restrict__ offset, int* __restrict__ rowptr) {
    __shared__ int sm[256];
    int t = threadIdx.x;
    int v = (t < NB) ? partial[t] : 0;
    sm[t] = v;
    __syncthreads();
#pragma unroll
    for (int off = 1; off < 256; off <<= 1) {
        int x = (t >= off) ? sm[t - off] : 0;
        __syncthreads();
        sm[t] += x;
        __syncthreads();
    }
    if (t < NB) offset[t] = sm[t] - v;
    if (t == 0) rowptr[NN] = EE;
}

__global__ void scan_final_kernel(const int* __restrict__ deg, const int* __restrict__ offset,
                                  int* __restrict__ rowptr, int* __restrict__ cursor) {
    __shared__ int sm[SCAN_CHUNK];
    int b = blockIdx.x, t = threadIdx.x;
    int i = b * SCAN_CHUNK + t;
    int v = (i < NN) ? deg[i] : 0;
    sm[t] = v;
    __syncthreads();
#pragma unroll
    for (int off = 1; off < SCAN_CHUNK; off <<= 1) {
        int x = (t >= off) ? sm[t - off] : 0;
        __syncthreads();
        sm[t] += x;
        __syncthreads();
    }
    if (i < NN) {
        int excl = sm[t] - v + offset[b];
        rowptr[i] = excl;
        cursor[i] = excl;
    }
}

__global__ void fill_csr_kernel(const int* __restrict__ src, const int* __restrict__ dst,
                                int* __restrict__ cursor, int* __restrict__ csr_src) {
    int i = blockIdx.x * blockDim.x + threadIdx.x;
    int stride = gridDim.x * blockDim.x;
    for (; i < EE; i += stride) {
        int d = dst[i];
        int slot = atomicAdd(&cursor[d], 1);
        csr_src[slot] = src[i];
    }
}

// ---------------- tensor-core GEMM (mma.sync m16n8k16, fp16 in / fp32 acc) ----------------
// C[n, M=HH*C] = A[n,K] @ B[K,M].  Block tile 128x64, 8 warps (2 M x 4 N),
// warp tile 64x16. Full-K smem resident (K<=128). Epilogue: acc -> smem h tile
// -> fp16 global store + fused attention dot products.
template <int K, int C>
__global__ void __launch_bounds__(256) gemm_mma_kernel(
        const __half* __restrict__ A, const __half* __restrict__ B,
        __half* __restrict__ Cout, int n,
        const float* __restrict__ att_s, const float* __restrict__ att_d,
        float* __restrict__ as_o, float* __restrict__ ad_o) {
    constexpr int M = HH * C;
    constexpr int CPR = K / 8;                 // 16B chunks per A row
    __shared__ __half As[128 * K];             // swizzled A tile; reused as h tile
    __shared__ __half Bs[K * 64];              // swizzled B tile

    const int tid = threadIdx.x;
    const int lane = tid & 31;
    const int warp = tid >> 5;
    const int mwarp = warp & 1;                // 0..1
    const int nwarp = warp >> 1;               // 0..3
    const int rowBase = blockIdx.y * 128;
    const int colBase = blockIdx.x * 64;

    // ---- load A tile (swizzle: chunk ^= row&7) ----
    for (int idx = tid; idx < 128 * CPR; idx += 256) {
        int r = idx / CPR, c = idx % CPR;
        int rg = rowBase + r;
        uint4 v = make_uint4(0u, 0u, 0u, 0u);
        if (rg < n) v = *(const uint4*)(A + (size_t)rg * K + c * 8);
        ((uint4*)As)[r * CPR + (c ^ (r & 7))] = v;
    }
    // ---- load B tile ----
    for (int idx = tid; idx < K * 8; idx += 256) {
        int r = idx >> 3, c = idx & 7;
        uint4 v = *(const uint4*)(B + (size_t)r * M + colBase + c * 8);
        ((uint4*)Bs)[r * 8 + (c ^ (r & 7))] = v;
    }
    __syncthreads();

    uint32_t asbase = (uint32_t)__cvta_generic_to_shared(As);
    uint32_t bsbase = (uint32_t)__cvta_generic_to_shared(Bs);

    float acc[4][2][4];
#pragma unroll
    for (int mt = 0; mt < 4; mt++)
#pragma unroll
        for (int nt = 0; nt < 2; nt++)
#pragma unroll
            for (int q = 0; q < 4; q++) acc[mt][nt][q] = 0.f;

#pragma unroll
    for (int ks = 0; ks < K / 16; ks++) {
        uint32_t af[4][4];
#pragma unroll
        for (int mt = 0; mt < 4; mt++) {
            int m0 = mwarp * 64 + mt * 16;
            int r = m0 + (lane & 7) + (lane & 8);
            int chunk = ks * 2 + (lane >> 4);
            int swz = chunk ^ (r & 7);
            uint32_t addr = asbase + (uint32_t)(r * K + swz * 8) * 2u;
            asm volatile("ldmatrix.sync.aligned.m8n8.x4.shared.b16 {%0,%1,%2,%3}, [%4];"
                         : "=r"(af[mt][0]), "=r"(af[mt][1]), "=r"(af[mt][2]), "=r"(af[mt][3])
                         : "r"(addr));
        }
        uint32_t bf[2][2];
#pragma unroll
        for (int nt = 0; nt < 2; nt++) {
            int n0 = nwarp * 16 + nt * 8;
            int l = lane & 15;
            int r = ks * 16 + (l & 7) + (l & 8);
            int swz = (n0 >> 3) ^ (r & 7);
            uint32_t addr = bsbase + (uint32_t)(r * 64 + swz * 8) * 2u;
            asm volatile("ldmatrix.sync.aligned.m8n8.x2.trans.shared.b16 {%0,%1}, [%2];"
                         : "=r"(bf[nt][0]), "=r"(bf[nt][1])
                         : "r"(addr));
        }
#pragma unroll
        for (int mt = 0; mt < 4; mt++)
#pragma unroll
            for (int nt = 0; nt < 2; nt++) {
                asm volatile(
                    "mma.sync.aligned.m16n8k16.row.col.f32.f16.f16.f32 "
                    "{%0,%1,%2,%3}, {%4,%5,%6,%7}, {%8,%9}, {%0,%1,%2,%3};"
                    : "+f"(acc[mt][nt][0]), "+f"(acc[mt][nt][1]),
                      "+f"(acc[mt][nt][2]), "+f"(acc[mt][nt][3])
                    : "r"(af[mt][0]), "r"(af[mt][1]), "r"(af[mt][2]), "r"(af[mt][3]),
                      "r"(bf[nt][0]), "r"(bf[nt][1]));
            }
    }

    __syncthreads();                 // all warps done reading As/Bs
    __half* htile = As;              // reuse as [128][64] h tile
    {
        int gid = lane >> 2, tig = lane & 3;
#pragma unroll
        for (int mt = 0; mt < 4; mt++)
#pragma unroll
            for (int nt = 0; nt < 2; nt++) {
                int r0 = mwarp * 64 + mt * 16 + gid;
                int c0 = nwarp * 16 + nt * 8 + tig * 2;
                *(__half2*)(htile + r0 * 64 + c0) =
                    __float22half2_rn(make_float2(acc[mt][nt][0], acc[mt][nt][1]));
                *(__half2*)(htile + (r0 + 8) * 64 + c0) =
                    __float22half2_rn(make_float2(acc[mt][nt][2], acc[mt][nt][3]));
            }
    }
    __syncthreads();

    // ---- att dots + global h store: 2 threads per row, 32 cols each ----
    {
        int r = tid >> 1, hf = tid & 1;
        int rg = rowBase + r;
        int head = (C == 64) ? blockIdx.x : (blockIdx.x * 2 + hf);
        const __half2* hp = (const __half2*)(htile + r * 64 + hf * 32);
        const float* sa = att_s + head * C + ((C == 64) ? hf * 32 : 0);
        const float* da = att_d + head * C + ((C == 64) ? hf * 32 : 0);
        float ps = 0.f, pd = 0.f;
#pragma unroll
        for (int j = 0; j < 16; j++) {
            float2 u = __half22float2(hp[j]);
            ps += u.x * sa[2 * j] + u.y * sa[2 * j + 1];
            pd += u.x * da[2 * j] + u.y * da[2 * j + 1];
        }
        if (C == 64) {
            ps += __shfl_xor_sync(0xffffffffu, ps, 1);
            pd += __shfl_xor_sync(0xffffffffu, pd, 1);
        }
        if (rg < n) {
            const uint4* srcp = (const uint4*)(htile + r * 64 + hf * 32);
            uint4* dstp = (uint4*)(Cout + (size_t)rg * M + colBase + hf * 32);
#pragma unroll
            for (int q = 0; q < 4; q++) dstp[q] = srcp[q];
            if (C == 32 || hf == 0) {
                as_o[rg * HH + head] = ps;
                ad_o[rg * HH + head] = pd;
            }
        }
    }
}

// ---------------- fused pull-mode GAT aggregation (fp16 gather, unroll 8) ----------------
// One block per destination node; NT = HH*C/2 threads; thread t owns channels
// [2t, 2t+1] (one half2). All accumulation in fp32. HOUT: fp16 output (layer1).
template <int C, bool HOUT>
__global__ void __launch_bounds__(HH * C / 2) gat_aggregate_kernel(
        const int* __restrict__ rowptr,
        const int* __restrict__ csr_src,
        const float* __restrict__ as_i,
        const float* __restrict__ ad_i,
        const __half2* __restrict__ feat,   // [N, HH*C/2]
        const float* __restrict__ bias,
        void* __restrict__ outp, int do_relu) {
    constexpr int NT = HH * C / 2;
    __shared__ float sm[HH * C];
    const int node = blockIdx.x;
    const int t = threadIdx.x;
    const int head = (2 * t) / C;
    const float adh = ad_i[node * HH + head];
    int beg = rowptr[node], end = rowptr[node + 1];
    float acc0 = 0.f, acc1 = 0.f, denom = 0.f;

    int e = beg;
    for (; e + 8 <= end; e += 8) {
        int s[8]; float a[8]; __half2 u[8];
#pragma unroll
        for (int q = 0; q < 8; q++) s[q] = __ldg(&csr_src[e + q]);
#pragma unroll
        for (int q = 0; q < 8; q++) u[q] = feat[(size_t)s[q] * NT + t];
#pragma unroll
        for (int q = 0; q < 8; q++) a[q] = __ldg(&as_i[s[q] * HH + head]);
#pragma unroll
        for (int q = 0; q < 8; q++) {
            float eq = a[q] + adh; eq = eq > 0.f ? eq : NEG_SLOPE * eq;
            float xq = __expf(eq);
            float2 uf = __half22float2(u[q]);
            denom += xq;
            acc0 += xq * uf.x;
            acc1 += xq * uf.y;
        }
    }
    for (; e + 4 <= end; e += 4) {
        int s[4]; float a[4]; __half2 u[4];
#pragma unroll
        for (int q = 0; q < 4; q++) s[q] = __ldg(&csr_src[e + q]);
#pragma unroll
        for (int q = 0; q < 4; q++) u[q] = feat[(size_t)s[q] * NT + t];
#pragma unroll
        for (int q = 0; q < 4; q++) a[q] = __ldg(&as_i[s[q] * HH + head]);
#pragma unroll
        for (int q = 0; q < 4; q++) {
            float eq = a[q] + adh; eq = eq > 0.f ? eq : NEG_SLOPE * eq;
            float xq = __expf(eq);
            float2 uf = __half22float2(u[q]);
            denom += xq;
            acc0 += xq * uf.x;
            acc1 += xq * uf.y;
        }
    }
    for (; e < end; e++) {
        int s0 = __ldg(&csr_src[e]);
        float a0 = __ldg(&as_i[s0 * HH + head]);
        float2 u0 = __half22float2(feat[(size_t)s0 * NT + t]);
        float e0 = a0 + adh; e0 = e0 > 0.f ? e0 : NEG_SLOPE * e0;
        float x0 = __expf(e0);
        denom += x0;
        acc0 += x0 * u0.x;
        acc1 += x0 * u0.y;
    }

    float inv = 1.f / (denom + EPSV);
    sm[2 * t]     = acc0 * inv;
    sm[2 * t + 1] = acc1 * inv;
    __syncthreads();
    if (t < C) {
        float v = 0.25f * (sm[t] + sm[C + t] + sm[2 * C + t] + sm[3 * C + t]) + bias[t];
        if (do_relu) v = fmaxf(v, 0.f);
        if (HOUT) ((__half*)outp)[(size_t)node * C + t] = __float2half(v);
        else      ((float*)outp)[(size_t)node * C + t] = v;
    }
}

// ---------------- host launcher ----------------
extern "C" void kernel_launch(void* const* d_in, const int* in_sizes, int n_in,
                              void* d_out, int out_size) {
    const float* x   = (const float*)d_in[0];
    const void*  ei  = d_in[1];
    const float* W1  = (const float*)d_in[2];
    const float* as1 = (const float*)d_in[3];
    const float* ad1 = (const float*)d_in[4];
    const float* b1  = (const float*)d_in[5];
    const float* W2  = (const float*)d_in[6];
    const float* as2 = (const float*)d_in[7];
    const float* ad2 = (const float*)d_in[8];
    const float* b2  = (const float*)d_in[9];
    float* out = (float*)d_out;

    __half *feat, *hmid, *xh, *w1h, *w2h;
    float *asb, *adb;
    int *srcp, *dstp, *deg, *rowptr, *cursor, *csr, *partial, *offset;
    cudaGetSymbolAddress((void**)&feat,    g_feat);
    cudaGetSymbolAddress((void**)&hmid,    g_hmid);
    cudaGetSymbolAddress((void**)&xh,      g_xh);
    cudaGetSymbolAddress((void**)&w1h,     g_w1h);
    cudaGetSymbolAddress((void**)&w2h,     g_w2h);
    cudaGetSymbolAddress((void**)&asb,     g_as);
    cudaGetSymbolAddress((void**)&adb,     g_ad);
    cudaGetSymbolAddress((void**)&srcp,    g_src);
    cudaGetSymbolAddress((void**)&dstp,    g_dst);
    cudaGetSymbolAddress((void**)&deg,     g_deg);
    cudaGetSymbolAddress((void**)&rowptr,  g_rowptr);
    cudaGetSymbolAddress((void**)&cursor,  g_cursor);
    cudaGetSymbolAddress((void**)&csr,     g_csr_src);
    cudaGetSymbolAddress((void**)&partial, g_partial);
    cudaGetSymbolAddress((void**)&offset,  g_offset);

    // ---- fp16 conversions ----
    f2h_kernel<<<1024, 256>>>(x,  xh,  NN * FIN / 4);
    f2h_kernel<<<32,   256>>>(W1, w1h, FIN * HH * CC1 / 4);
    f2h_kernel<<<8,    256>>>(W2, w2h, CC1 * HH * CC2 / 4);

    // ---- CSR build ----
    cudaMemsetAsync(deg, 0, NN * sizeof(int));
    decode_hist_kernel<<<1024, 256>>>(ei, srcp, dstp, deg);
    scan_partials_kernel<<<NB, SCAN_CHUNK>>>(deg, partial);
    scan_offsets_kernel<<<1, 256>>>(partial, offset, rowptr);
    scan_final_kernel<<<NB, SCAN_CHUNK>>>(deg, offset, rowptr, cursor);
    fill_csr_kernel<<<512, 256>>>(srcp, dstp, cursor, csr);

    const int rowBlocks = (NN + 127) / 128;   // 391

    // ---- layer 1 ----
    gemm_mma_kernel<FIN, CC1><<<dim3(HH * CC1 / 64, rowBlocks), 256>>>(
        xh, w1h, feat, NN, as1, ad1, asb, adb);
    gat_aggregate_kernel<CC1, true><<<NN, HH * CC1 / 2>>>(
        rowptr, csr, asb, adb, (const __half2*)feat, b1, hmid, 1);

    // ---- layer 2 ----
    gemm_mma_kernel<CC1, CC2><<<dim3(HH * CC2 / 64, rowBlocks), 256>>>(
        hmid, w2h, feat, NN, as2, ad2, asb, adb);
    gat_aggregate_kernel<CC2, false><<<NN, HH * CC2 / 2>>>(
        rowptr, csr, asb, adb, (const __half2*)feat, b2, out, 0);
}